// round 1
// baseline (speedup 1.0000x reference)
#include <cuda_runtime.h>
#include <math.h>

// Problem dims
#define M_ROWS  8192      // 4 * 2048
#define N_ATOMS 16384
#define DM      1024
#define NEG_INF (-1e9f)

// 512 MB scratch for scores / weights
__device__ float g_scores[(size_t)M_ROWS * N_ATOMS];

// ---------------------------------------------------------------------------
// K1: scores[m, a] = sum_k X[m,k] * Dict[a,k], then mask -> -1e9
// Tiling: 128x128 block tile, BK=8, 256 threads, 8x8 per thread.
// Both X and Dict are K-contiguous -> identical coalesced transpose loads.
// ---------------------------------------------------------------------------
__global__ __launch_bounds__(256) void scores_kernel(
    const float* __restrict__ X, const float* __restrict__ Dm,
    const int* __restrict__ mask, float* __restrict__ S)
{
    __shared__ float As[8][128];
    __shared__ float Bs[8][128];

    const int bm = blockIdx.y * 128;
    const int bn = blockIdx.x * 128;
    const int tid = threadIdx.x;

    const int lm = tid >> 1;            // row within tile for loading (0..127)
    const int lk = (tid & 1) * 4;       // k quad (0 or 4)

    const int tm = (tid >> 4) * 8;      // 16x16 thread grid, 8x8 micro-tile
    const int tn = (tid & 15) * 8;

    float acc[8][8];
    #pragma unroll
    for (int i = 0; i < 8; i++)
        #pragma unroll
        for (int j = 0; j < 8; j++) acc[i][j] = 0.0f;

    const float* aptr = X  + (size_t)(bm + lm) * DM + lk;
    const float* bptr = Dm + (size_t)(bn + lm) * DM + lk;

    for (int k0 = 0; k0 < DM; k0 += 8) {
        float4 av = *reinterpret_cast<const float4*>(aptr + k0);
        float4 bv = *reinterpret_cast<const float4*>(bptr + k0);
        __syncthreads();
        As[lk + 0][lm] = av.x; As[lk + 1][lm] = av.y;
        As[lk + 2][lm] = av.z; As[lk + 3][lm] = av.w;
        Bs[lk + 0][lm] = bv.x; Bs[lk + 1][lm] = bv.y;
        Bs[lk + 2][lm] = bv.z; Bs[lk + 3][lm] = bv.w;
        __syncthreads();

        #pragma unroll
        for (int k = 0; k < 8; k++) {
            float a[8], b[8];
            #pragma unroll
            for (int i = 0; i < 8; i++) a[i] = As[k][tm + i];
            #pragma unroll
            for (int j = 0; j < 8; j++) b[j] = Bs[k][tn + j];
            #pragma unroll
            for (int i = 0; i < 8; i++)
                #pragma unroll
                for (int j = 0; j < 8; j++)
                    acc[i][j] = fmaf(a[i], b[j], acc[i][j]);
        }
    }

    // Epilogue: apply mask, write scores
    #pragma unroll
    for (int i = 0; i < 8; i++) {
        const size_t row = (size_t)(bm + tm + i);
        #pragma unroll
        for (int j = 0; j < 8; j += 4) {
            const size_t col = (size_t)(bn + tn + j);
            int4 mv = *reinterpret_cast<const int4*>(&mask[row * N_ATOMS + col]);
            float4 ov;
            ov.x = mv.x ? acc[i][j + 0] : NEG_INF;
            ov.y = mv.y ? acc[i][j + 1] : NEG_INF;
            ov.z = mv.z ? acc[i][j + 2] : NEG_INF;
            ov.w = mv.w ? acc[i][j + 3] : NEG_INF;
            *reinterpret_cast<float4*>(&S[row * N_ATOMS + col]) = ov;
        }
    }
}

// ---------------------------------------------------------------------------
// K2: per-row max+argmax (first-occurrence ties like jnp.argmax), then
// softmax in place. One block (256 threads) per row of 16384.
// ---------------------------------------------------------------------------
__global__ __launch_bounds__(256) void softmax_argmax_kernel(
    float* __restrict__ S, float* __restrict__ argmax_out)
{
    const int row = blockIdx.x;
    float* s = S + (size_t)row * N_ATOMS;
    const int tid = threadIdx.x;

    __shared__ float sv[256];
    __shared__ int   si[256];

    // Pass 1: max + argmax (strict > keeps smallest index per thread;
    // reduction tie-breaks to smaller index)
    float best = -INFINITY; int besti = 0;
    for (int c0 = tid * 4; c0 < N_ATOMS; c0 += 1024) {
        float4 v = *reinterpret_cast<const float4*>(s + c0);
        if (v.x > best) { best = v.x; besti = c0 + 0; }
        if (v.y > best) { best = v.y; besti = c0 + 1; }
        if (v.z > best) { best = v.z; besti = c0 + 2; }
        if (v.w > best) { best = v.w; besti = c0 + 3; }
    }
    sv[tid] = best; si[tid] = besti;
    __syncthreads();
    for (int off = 128; off > 0; off >>= 1) {
        if (tid < off) {
            float ov = sv[tid + off]; int oi = si[tid + off];
            if (ov > sv[tid] || (ov == sv[tid] && oi < si[tid])) {
                sv[tid] = ov; si[tid] = oi;
            }
        }
        __syncthreads();
    }
    const float rmax = sv[0];
    if (tid == 0) argmax_out[row] = (float)si[0];
    __syncthreads();

    // Pass 2: sum of exp
    float lsum = 0.0f;
    for (int c0 = tid * 4; c0 < N_ATOMS; c0 += 1024) {
        float4 v = *reinterpret_cast<const float4*>(s + c0);
        lsum += expf(v.x - rmax) + expf(v.y - rmax)
              + expf(v.z - rmax) + expf(v.w - rmax);
    }
    sv[tid] = lsum;
    __syncthreads();
    for (int off = 128; off > 0; off >>= 1) {
        if (tid < off) sv[tid] += sv[tid + off];
        __syncthreads();
    }
    const float inv = 1.0f / sv[0];

    // Pass 3: write normalized weights in place
    for (int c0 = tid * 4; c0 < N_ATOMS; c0 += 1024) {
        float4 v = *reinterpret_cast<float4*>(s + c0);
        v.x = expf(v.x - rmax) * inv;
        v.y = expf(v.y - rmax) * inv;
        v.z = expf(v.z - rmax) * inv;
        v.w = expf(v.w - rmax) * inv;
        *reinterpret_cast<float4*>(s + c0) = v;
    }
}

// ---------------------------------------------------------------------------
// K3: recon[m, d] = sum_a W[m,a] * Dict[a,d]
// W is K-contiguous (transpose load like K1's A); Dict is N-contiguous here.
// ---------------------------------------------------------------------------
__global__ __launch_bounds__(256) void recon_kernel(
    const float* __restrict__ W, const float* __restrict__ Dm,
    float* __restrict__ O)
{
    __shared__ float As[8][128];
    __shared__ float Bs[8][128];

    const int bm = blockIdx.y * 128;
    const int bn = blockIdx.x * 128;
    const int tid = threadIdx.x;

    const int lm = tid >> 1;
    const int lk = (tid & 1) * 4;

    const int bk = tid >> 5;            // 0..7 : k-row for B load
    const int bn4 = (tid & 31) * 4;     // 0..124 : n quad for B load

    const int tm = (tid >> 4) * 8;
    const int tn = (tid & 15) * 8;

    float acc[8][8];
    #pragma unroll
    for (int i = 0; i < 8; i++)
        #pragma unroll
        for (int j = 0; j < 8; j++) acc[i][j] = 0.0f;

    const float* aptr = W + (size_t)(bm + lm) * N_ATOMS + lk;

    for (int k0 = 0; k0 < N_ATOMS; k0 += 8) {
        float4 av = *reinterpret_cast<const float4*>(aptr + k0);
        float4 bv = *reinterpret_cast<const float4*>(
            &Dm[(size_t)(k0 + bk) * DM + bn + bn4]);
        __syncthreads();
        As[lk + 0][lm] = av.x; As[lk + 1][lm] = av.y;
        As[lk + 2][lm] = av.z; As[lk + 3][lm] = av.w;
        *reinterpret_cast<float4*>(&Bs[bk][bn4]) = bv;
        __syncthreads();

        #pragma unroll
        for (int k = 0; k < 8; k++) {
            float a[8], b[8];
            #pragma unroll
            for (int i = 0; i < 8; i++) a[i] = As[k][tm + i];
            #pragma unroll
            for (int j = 0; j < 8; j++) b[j] = Bs[k][tn + j];
            #pragma unroll
            for (int i = 0; i < 8; i++)
                #pragma unroll
                for (int j = 0; j < 8; j++)
                    acc[i][j] = fmaf(a[i], b[j], acc[i][j]);
        }
    }

    #pragma unroll
    for (int i = 0; i < 8; i++) {
        const size_t row = (size_t)(bm + tm + i);
        #pragma unroll
        for (int j = 0; j < 8; j += 4) {
            float4 ov = make_float4(acc[i][j], acc[i][j + 1],
                                    acc[i][j + 2], acc[i][j + 3]);
            *reinterpret_cast<float4*>(&O[row * DM + bn + tn + j]) = ov;
        }
    }
}

// ---------------------------------------------------------------------------
// Launch: X [8192,1024] f32, Dict [16384,1024] f32, mask [8192,16384] i32.
// Output: recon (8192*1024 f32) followed by argmax indices as f32 (8192).
// ---------------------------------------------------------------------------
extern "C" void kernel_launch(void* const* d_in, const int* in_sizes, int n_in,
                              void* d_out, int out_size)
{
    const float* X    = (const float*)d_in[0];
    const float* Dict = (const float*)d_in[1];
    const int*   mask = (const int*)d_in[2];
    float* out = (float*)d_out;

    float* scores = nullptr;
    cudaGetSymbolAddress((void**)&scores, g_scores);

    float* recon_out  = out;
    float* argmax_out = out + (size_t)M_ROWS * DM;

    {
        dim3 grid(N_ATOMS / 128, M_ROWS / 128);
        scores_kernel<<<grid, 256>>>(X, Dict, mask, scores);
    }
    {
        softmax_argmax_kernel<<<M_ROWS, 256>>>(scores, argmax_out);
    }
    {
        dim3 grid(DM / 128, M_ROWS / 128);
        recon_kernel<<<grid, 256>>>(scores, Dict, recon_out);
    }
}